// round 16
// baseline (speedup 1.0000x reference)
#include <cuda_runtime.h>
#include <cuda_fp16.h>
#include <cstdint>

// B=4096, D(K)=2048, C=16384, topk=64
// recon = TopK(BN(x @ W_enc^T)) @ normalize_cols(W_dec)^T + b_dec
// b_enc cancels inside batch-norm -> skipped everywhere (consistent).
//
// Numerics ledger (R4..R15):
//  - BN stats: fp64 reduction of split-fp16 fp32 GEMM accumulators.
//  - Candidates tolerate ~7e-4 -> h stored fp16, margin 16.
//  - Refinement: serial ascending-k fp32 FMA chain, values bit-fixed (R7/R8).
//  - GEMM: R11 inner order optimal (R12/R14 falsified reorders).
//  - WnT fp16: +2e-4 rel_err, fine (R15).
// R16: refine pairs counting-sorted by W_enc column -> warp-broadcast gathers.

#define MAX_B 4096
#define MAX_C 16384
#define MAX_D 2048
#define MAX_MT 32
#define NCAND 160

__device__ __half g_h16[(size_t)MAX_B * MAX_C];
__device__ __half g_WnT16[(size_t)MAX_C * MAX_D];
__device__ float g_inv_norm[MAX_C];
__device__ float g_scale[MAX_C];
__device__ float g_bias[MAX_C];
__device__ double g_psum[MAX_MT * MAX_C];
__device__ double g_psumsq[MAX_MT * MAX_C];
__device__ __half g_xh[(size_t)MAX_B * MAX_D];
__device__ __half g_xl[(size_t)MAX_B * MAX_D];
__device__ __half g_wh[(size_t)MAX_C * MAX_D];
__device__ __half g_wl[(size_t)MAX_C * MAX_D];
__device__ int   g_candIdx[(size_t)MAX_B * NCAND];
__device__ float g_candVal[(size_t)MAX_B * NCAND];
__device__ int   g_candCnt[MAX_B];
// column-sorted pair machinery
__device__ int g_colHist[MAX_C];
__device__ int g_colOffset[MAX_C];
__device__ int g_totalPairs;
__device__ int g_pairRowSlot[(size_t)MAX_B * NCAND];
__device__ int g_pairCol[(size_t)MAX_B * NCAND];

// ---------------------------------------------------------------------------
__global__ void split_all_kernel(const float* __restrict__ x,
                                 const float* __restrict__ W, int nx, int nw) {
    int i = blockIdx.x * blockDim.x + threadIdx.x;
    if (i < nx) {
        float s = x[i] * 4096.0f;                // 2^12, exact
        __half h = __float2half_rn(s);
        g_xh[i] = h;
        g_xl[i] = __float2half_rn(s - __half2float(h));
    } else if (i < nx + nw) {
        int j = i - nx;
        float s = W[j] * 262144.0f;              // 2^18, exact
        __half h = __float2half_rn(s);
        g_wh[j] = h;
        g_wl[j] = __float2half_rn(s - __half2float(h));
    }
}

// ---------------------------------------------------------------------------
// colnorm (+ zero column histogram for the later pair sort)
// ---------------------------------------------------------------------------
__global__ void colnorm_kernel(const float* __restrict__ Wdec, int D, int C) {
    int c = blockIdx.x * blockDim.x + threadIdx.x;
    if (c >= C) return;
    g_colHist[c] = 0;
    double s0 = 0, s1 = 0, s2 = 0, s3 = 0;
    int d = 0;
    for (; d + 3 < D; d += 4) {
        float w0 = Wdec[(size_t)(d + 0) * C + c];
        float w1 = Wdec[(size_t)(d + 1) * C + c];
        float w2 = Wdec[(size_t)(d + 2) * C + c];
        float w3 = Wdec[(size_t)(d + 3) * C + c];
        s0 += (double)w0 * w0; s1 += (double)w1 * w1;
        s2 += (double)w2 * w2; s3 += (double)w3 * w3;
    }
    for (; d < D; d++) { float w = Wdec[(size_t)d * C + c]; s0 += (double)w * w; }
    double n = sqrt(s0 + s1 + s2 + s3);
    if (n < 1e-12) n = 1e-12;
    g_inv_norm[c] = (float)(1.0 / n);
}

// ---------------------------------------------------------------------------
__global__ void transpose_kernel(const float* __restrict__ Wdec, int D, int C) {
    __shared__ float tile[32][33];
    int c0 = blockIdx.x * 32, d0 = blockIdx.y * 32;
    for (int i = threadIdx.y; i < 32; i += 8) {
        int d = d0 + i, c = c0 + threadIdx.x;
        tile[i][threadIdx.x] = (d < D && c < C) ? Wdec[(size_t)d * C + c] : 0.f;
    }
    __syncthreads();
    for (int i = threadIdx.y; i < 32; i += 8) {
        int c = c0 + i, d = d0 + threadIdx.x;
        if (c < C && d < D)
            g_WnT16[(size_t)c * D + d] =
                __float2half_rn(tile[threadIdx.x][i] * g_inv_norm[c]);
    }
}

// ---------------------------------------------------------------------------
// mma.sync split-fp16 GEMM (R11 inner order — best measured: 2156us)
// ---------------------------------------------------------------------------
#define BKH 32
#define MAT_BYTES 8192
#define STAGE_BYTES 32768
#define STAGES 3
#define GEMM_SMEM (STAGES * STAGE_BYTES)

#define LDSM4(R0, R1, R2, R3, ADDR) \
    asm volatile("ldmatrix.sync.aligned.m8n8.x4.shared.b16 {%0,%1,%2,%3}, [%4];" \
                 : "=r"(R0), "=r"(R1), "=r"(R2), "=r"(R3) : "r"(ADDR))

#define MMA16816(CC, A0, A1, A2, A3, B0, B1) \
    asm volatile("mma.sync.aligned.m16n8k16.row.col.f32.f16.f16.f32 " \
                 "{%0,%1,%2,%3}, {%4,%5,%6,%7}, {%8,%9}, {%0,%1,%2,%3};" \
                 : "+f"((CC)[0]), "+f"((CC)[1]), "+f"((CC)[2]), "+f"((CC)[3]) \
                 : "r"(A0), "r"(A1), "r"(A2), "r"(A3), "r"(B0), "r"(B1))

__device__ __forceinline__ uint32_t smem_u32(const void* p) {
    uint32_t a;
    asm("{ .reg .u64 t; cvta.to.shared.u64 t, %1; cvt.u32.u64 %0, t; }" : "=r"(a) : "l"(p));
    return a;
}
__device__ __forceinline__ uint32_t swz64(uint32_t base, int row, int kbyte) {
    uint32_t off = row * 64 + kbyte;
    return base + (off ^ ((off >> 3) & 0x30));
}
__device__ __forceinline__ void cpasync16(uint32_t sa, const void* g) {
    asm volatile("cp.async.cg.shared.global [%0], [%1], 16;" :: "r"(sa), "l"(g));
}

__device__ __forceinline__ void load_stage(uint32_t sbase, int m0, int n0,
                                           int k0, int K, int tid) {
    const __half* srcs[4] = {g_xh, g_xl, g_wh, g_wl};
    int r0s[4] = {m0, m0, n0, n0};
#pragma unroll
    for (int mat = 0; mat < 4; mat++) {
        const __half* src = srcs[mat];
        int r0 = r0s[mat];
#pragma unroll
        for (int s = 0; s < 2; s++) {
            int idx = tid * 2 + s;
            int row = idx >> 2, seg = idx & 3;
            const __half* g = src + (size_t)(r0 + row) * K + k0 + seg * 8;
            cpasync16(swz64(sbase + mat * MAT_BYTES, row, seg * 16), g);
        }
    }
}

__global__ __launch_bounds__(256, 2)
void hgemm_kernel(int M, int N, int K) {
    extern __shared__ __align__(1024) char smem[];
    const uint32_t sb = smem_u32(smem);
    const int tid = threadIdx.x;
    const int wid = tid >> 5, lane = tid & 31;
    const int wm = (wid & 1) * 64;
    const int wn = (wid >> 1) * 32;
    const int m0 = blockIdx.x * 128;
    const int n0 = blockIdx.y * 128;
    const int grp = lane >> 3, lr = lane & 7;
    const int NK = K / BKH;

    float acc[4][4][4];
#pragma unroll
    for (int i = 0; i < 4; i++)
#pragma unroll
        for (int j = 0; j < 4; j++)
#pragma unroll
            for (int q = 0; q < 4; q++) acc[i][j][q] = 0.f;

#pragma unroll
    for (int s = 0; s < STAGES - 1; s++) {
        load_stage(sb + s * STAGE_BYTES, m0, n0, s * BKH, K, tid);
        asm volatile("cp.async.commit_group;");
    }

    for (int ch = 0; ch < NK; ch++) {
        asm volatile("cp.async.wait_group %0;" :: "n"(STAGES - 2));
        __syncthreads();

        int pf = ch + STAGES - 1;
        if (pf < NK)
            load_stage(sb + (pf % STAGES) * STAGE_BYTES, m0, n0, pf * BKH, K, tid);
        asm volatile("cp.async.commit_group;");

        uint32_t sa = sb + (ch % STAGES) * STAGE_BYTES;
        uint32_t aH = sa, aL = sa + MAT_BYTES;
        uint32_t bH = sa + 2 * MAT_BYTES, bL = sa + 3 * MAT_BYTES;

#pragma unroll
        for (int ks = 0; ks < 2; ks++) {
            int kb = ks * 32;
            uint32_t Bh[4][2], Bl[4][2];
#pragma unroll
            for (int np = 0; np < 2; np++) {
                int nrow = wn + np * 16 + (grp >> 1) * 8 + lr;
                int kbyte = kb + (grp & 1) * 16;
                uint32_t r0, r1, r2, r3;
                LDSM4(r0, r1, r2, r3, swz64(bH, nrow, kbyte));
                Bh[np * 2][0] = r0; Bh[np * 2][1] = r1;
                Bh[np * 2 + 1][0] = r2; Bh[np * 2 + 1][1] = r3;
                LDSM4(r0, r1, r2, r3, swz64(bL, nrow, kbyte));
                Bl[np * 2][0] = r0; Bl[np * 2][1] = r1;
                Bl[np * 2 + 1][0] = r2; Bl[np * 2 + 1][1] = r3;
            }
#pragma unroll
            for (int mi = 0; mi < 4; mi++) {
                int arow = wm + mi * 16 + (grp & 1) * 8 + lr;
                int kbyte = kb + (grp >> 1) * 16;
                uint32_t a0, a1, a2, a3, l0, l1, l2, l3;
                LDSM4(a0, a1, a2, a3, swz64(aH, arow, kbyte));
                LDSM4(l0, l1, l2, l3, swz64(aL, arow, kbyte));
#pragma unroll
                for (int ni = 0; ni < 4; ni++)
                    MMA16816(acc[mi][ni], a0, a1, a2, a3, Bh[ni][0], Bh[ni][1]);
#pragma unroll
                for (int ni = 0; ni < 4; ni++)
                    MMA16816(acc[mi][ni], a0, a1, a2, a3, Bl[ni][0], Bl[ni][1]);
#pragma unroll
                for (int ni = 0; ni < 4; ni++)
                    MMA16816(acc[mi][ni], l0, l1, l2, l3, Bh[ni][0], Bh[ni][1]);
            }
        }
        __syncthreads();
    }

    const float sc = 9.313225746154785e-10f;  // 2^-30
    int gid = lane >> 2, tig = lane & 3;
#pragma unroll
    for (int mi = 0; mi < 4; mi++) {
#pragma unroll
        for (int ni = 0; ni < 4; ni++) {
            int r = m0 + wm + mi * 16 + gid;
            int c = n0 + wn + ni * 8 + tig * 2;
            *(__half2*)&g_h16[(size_t)r * N + c] =
                __floats2half2_rn(acc[mi][ni][0] * sc, acc[mi][ni][1] * sc);
            *(__half2*)&g_h16[(size_t)(r + 8) * N + c] =
                __floats2half2_rn(acc[mi][ni][2] * sc, acc[mi][ni][3] * sc);
        }
    }

    double csum[4][2], csq[4][2];
#pragma unroll
    for (int ni = 0; ni < 4; ni++)
#pragma unroll
        for (int qc = 0; qc < 2; qc++) {
            double s = 0.0, q = 0.0;
#pragma unroll
            for (int mi = 0; mi < 4; mi++) {
                double v1 = (double)(acc[mi][ni][qc]) * (double)sc;
                double v2 = (double)(acc[mi][ni][qc + 2]) * (double)sc;
                s += v1 + v2;
                q += v1 * v1 + v2 * v2;
            }
            csum[ni][qc] = s; csq[ni][qc] = q;
        }
#pragma unroll
    for (int off = 4; off <= 16; off <<= 1) {
#pragma unroll
        for (int ni = 0; ni < 4; ni++)
#pragma unroll
            for (int qc = 0; qc < 2; qc++) {
                csum[ni][qc] += __shfl_xor_sync(0xffffffffu, csum[ni][qc], off);
                csq[ni][qc]  += __shfl_xor_sync(0xffffffffu, csq[ni][qc], off);
            }
    }
    __syncthreads();
    double* scs = (double*)smem;
    double* scq = scs + 256;
    if (gid == 0) {
#pragma unroll
        for (int ni = 0; ni < 4; ni++)
#pragma unroll
            for (int qc = 0; qc < 2; qc++) {
                int cl = wn + ni * 8 + tig * 2 + qc;
                scs[(wid & 1) * 128 + cl] = csum[ni][qc];
                scq[(wid & 1) * 128 + cl] = csq[ni][qc];
            }
    }
    __syncthreads();
    if (tid < 128) {
        int mt = blockIdx.x;
        g_psum[(size_t)mt * N + n0 + tid]   = scs[tid] + scs[128 + tid];
        g_psumsq[(size_t)mt * N + n0 + tid] = scq[tid] + scq[128 + tid];
    }
}

// ---------------------------------------------------------------------------
__global__ void stats_final_kernel(const float* __restrict__ gamma,
                                   const float* __restrict__ beta,
                                   int Bsz, int C, int nslot) {
    int c = blockIdx.x * blockDim.x + threadIdx.x;
    if (c >= C) return;
    double s = 0, q = 0;
    for (int i = 0; i < nslot; i++) {
        s += g_psum[(size_t)i * C + c];
        q += g_psumsq[(size_t)i * C + c];
    }
    double mean = s / (double)Bsz;
    double var = q / (double)Bsz - mean * mean;
    double inv = 1.0 / sqrt(var + 1e-5);
    float sc = (float)((double)gamma[c] * inv);
    g_scale[c] = sc;
    g_bias[c] = beta[c] - (float)mean * sc;
}

// ---------------------------------------------------------------------------
// topk_select (+ column histogram for pair sort)
// ---------------------------------------------------------------------------
__global__ __launch_bounds__(256) void topk_select_kernel(
    const int* __restrict__ topk_p, int C) {
    extern __shared__ float sm[];
    float* vals = sm;
    unsigned* hist = (unsigned*)(vals + C);
    unsigned* chunks = hist + 2048;

    __shared__ int s_selIdx[NCAND];
    __shared__ int s_eqIdx[256];
    __shared__ int s_nsel, s_neq, s_need, s_chunk, s_flagzero;
    __shared__ unsigned s_prefix;

    int row = blockIdx.x;
    int tid = threadIdx.x;
    int k = *topk_p;
    if (k > C) k = C;
    if (k > 128) k = 128;
    int kc = k + 16;
    if (kc > C) kc = C;
    if (kc > NCAND) kc = NCAND;

    for (int c = tid; c < C; c += 256) {
        float v = __half2float(g_h16[(size_t)row * C + c]);
        v = v * g_scale[c] + g_bias[c];
        vals[c] = (v > 0.f) ? v : 0.f;
    }
    if (tid == 0) { s_nsel = 0; s_neq = 0; s_need = kc; s_prefix = 0u; s_flagzero = 0; }
    __syncthreads();

    {
        const int shifts[3] = {21, 10, 0};
        const int nbitsA[3] = {11, 11, 10};
        const unsigned maskHi[3] = {0u, 0xFFE00000u, 0xFFFFFC00u};

        for (int r = 0; r < 3; r++) {
            int nb = 1 << nbitsA[r];
            for (int i = tid; i < nb; i += 256) hist[i] = 0u;
            __syncthreads();

            unsigned pre = s_prefix, mh = maskHi[r], msk = (unsigned)(nb - 1);
            int sh = shifts[r];
            for (int c = tid; c < C; c += 256) {
                unsigned key = __float_as_uint(vals[c]);
                if (key != 0u && (key & mh) == pre)
                    atomicAdd(&hist[(key >> sh) & msk], 1u);
            }
            __syncthreads();

            int NCH = nb >> 3;
            unsigned csum = 0u;
            if (tid < NCH) {
#pragma unroll
                for (int j = 0; j < 8; j++) csum += hist[tid * 8 + j];
                chunks[tid] = csum;
            }
            __syncthreads();
            for (int off = 1; off < NCH; off <<= 1) {
                unsigned add = 0u;
                if (tid < NCH && tid + off < NCH) add = chunks[tid + off];
                __syncthreads();
                if (tid < NCH) chunks[tid] += add;
                __syncthreads();
            }

            int need = s_need;
            if (tid < NCH) {
                int incl = (int)chunks[tid];
                int excl = incl - (int)csum;
                if (excl < need && incl >= need) s_chunk = tid;
                if (tid == 0 && incl < need) s_flagzero = 1;
            }
            __syncthreads();
            if (s_flagzero) break;

            if (tid == 0) {
                int t = s_chunk;
                unsigned cs = 0u;
#pragma unroll
                for (int j = 0; j < 8; j++) cs += hist[t * 8 + j];
                int cum = (int)chunks[t] - (int)cs;
                for (int j = 7; j >= 0; j--) {
                    int hc = (int)hist[t * 8 + j];
                    cum += hc;
                    if (cum >= need) {
                        s_prefix |= ((unsigned)(t * 8 + j)) << sh;
                        s_need = need - (cum - hc);
                        break;
                    }
                }
            }
            __syncthreads();
        }
        __syncthreads();

        unsigned T = s_prefix;
        int need_eq = s_need;
        bool zeroThresh = (s_flagzero != 0);

        for (int c = tid; c < C; c += 256) {
            unsigned key = __float_as_uint(vals[c]);
            if (key == 0u) continue;
            if (zeroThresh || key > T) {
                int p = atomicAdd(&s_nsel, 1);
                if (p < NCAND) s_selIdx[p] = c;
            } else if (key == T) {
                int p = atomicAdd(&s_neq, 1);
                if (p < 256) s_eqIdx[p] = c;
            }
        }
        __syncthreads();

        if (!zeroThresh && tid == 0) {
            int ne = s_neq; if (ne > 256) ne = 256;
            for (int i = 1; i < ne; i++) {
                int v = s_eqIdx[i]; int j = i - 1;
                while (j >= 0 && s_eqIdx[j] > v) { s_eqIdx[j + 1] = s_eqIdx[j]; j--; }
                s_eqIdx[j + 1] = v;
            }
            int take = need_eq; if (take > ne) take = ne;
            int base = s_nsel;
            for (int i = 0; i < take; i++) {
                int p = base + i;
                if (p < NCAND) s_selIdx[p] = s_eqIdx[i];
            }
            s_nsel = base + take;
        }
        __syncthreads();
    }

    int ncand = s_nsel; if (ncand > NCAND) ncand = NCAND;
    if (tid < ncand) {
        int col = s_selIdx[tid];
        g_candIdx[(size_t)row * NCAND + tid] = col;
        atomicAdd(&g_colHist[col], 1);
    }
    if (tid == 0) g_candCnt[row] = ncand;
}

// ---------------------------------------------------------------------------
// scan: exclusive prefix over column histogram (single block, deterministic)
// ---------------------------------------------------------------------------
__global__ void scan_kernel(int C) {
    __shared__ int part[256];
    int tid = threadIdx.x;
    int per = C / 256;
    int base = tid * per;
    int s = 0;
    for (int j = 0; j < per; j++) s += g_colHist[base + j];
    part[tid] = s;
    __syncthreads();
    int val = s;
    for (int off = 1; off < 256; off <<= 1) {
        int add = (tid >= off) ? part[tid - off] : 0;
        __syncthreads();
        part[tid] += add;
        __syncthreads();
    }
    int run = part[tid] - val;   // exclusive prefix of this chunk
    for (int j = 0; j < per; j++) {
        int h = g_colHist[base + j];
        g_colOffset[base + j] = run;
        run += h;
    }
    if (tid == 255) g_totalPairs = run;
}

// ---------------------------------------------------------------------------
// scatter: (row,slot) pairs into column-sorted order
// ---------------------------------------------------------------------------
__global__ void scatter_kernel() {
    int row = blockIdx.x, tid = threadIdx.x;
    int nc = g_candCnt[row]; if (nc > NCAND) nc = NCAND;
    if (tid < nc) {
        int col = g_candIdx[(size_t)row * NCAND + tid];
        int pos = atomicAdd(&g_colOffset[col], 1);
        g_pairRowSlot[pos] = (row << 8) | tid;
        g_pairCol[pos] = col;
    }
}

// ---------------------------------------------------------------------------
// refine2: column-sorted pairs -> warp-broadcast W_enc loads.
// Per-candidate serial ascending-k fp32 FMA chain (bit-identical values).
// ---------------------------------------------------------------------------
__global__ __launch_bounds__(256) void refine2_kernel(
    const float* __restrict__ x, const float* __restrict__ W_enc, int D) {
    int idx = blockIdx.x * blockDim.x + threadIdx.x;
    if (idx >= g_totalPairs) return;
    int rs = g_pairRowSlot[idx];
    int row = rs >> 8, slot = rs & 255;
    int col = g_pairCol[idx];

    const float4* wr = (const float4*)(W_enc + (size_t)col * D);
    const float4* xr = (const float4*)(x + (size_t)row * D);
    const int NIT = D >> 2;
    float facc = 0.f;
#pragma unroll 4
    for (int i = 0; i < NIT; i++) {
        float4 w = wr[i];
        float4 xq = xr[i];
        facc = __fmaf_rn(xq.x, w.x, facc);
        facc = __fmaf_rn(xq.y, w.y, facc);
        facc = __fmaf_rn(xq.z, w.z, facc);
        facc = __fmaf_rn(xq.w, w.w, facc);
    }
    float bn = __fmaf_rn(facc, g_scale[col], g_bias[col]);
    g_candVal[(size_t)row * NCAND + slot] = (bn > 0.f) ? bn : 0.f;
}

// ---------------------------------------------------------------------------
// decode: exact rank (value desc, index asc), fp16 WnT gather, 8 out/thread.
// ---------------------------------------------------------------------------
__global__ __launch_bounds__(256) void decode_kernel(
    const float* __restrict__ b_dec, const int* __restrict__ topk_p,
    float* __restrict__ out, int C, int D) {
    __shared__ int s_idx[NCAND];
    __shared__ float s_val[NCAND];
    __shared__ int s_fIdx[128];
    __shared__ float s_fVal[128];

    int row = blockIdx.x;
    int tid = threadIdx.x;
    int k = *topk_p;
    if (k > C) k = C;
    if (k > 128) k = 128;

    int ncand = g_candCnt[row];
    if (ncand > NCAND) ncand = NCAND;
    if (tid < ncand) {
        s_idx[tid] = g_candIdx[(size_t)row * NCAND + tid];
        s_val[tid] = g_candVal[(size_t)row * NCAND + tid];
    }
    __syncthreads();

    int kk = (k < ncand) ? k : ncand;
    if (tid < ncand) {
        float vj = s_val[tid]; int cj = s_idx[tid];
        int rank = 0;
        for (int i = 0; i < ncand; i++) {
            float vi = s_val[i]; int ci = s_idx[i];
            if (vi > vj || (vi == vj && ci < cj)) rank++;
        }
        if (rank < kk) { s_fVal[rank] = vj; s_fIdx[rank] = cj; }
    }
    __syncthreads();

    int d0 = tid * 8;   // D=2048 covered by 256 threads x 8
    if (d0 + 7 < D) {
        float a0 = b_dec[d0], a1 = b_dec[d0+1], a2 = b_dec[d0+2], a3 = b_dec[d0+3];
        float a4 = b_dec[d0+4], a5 = b_dec[d0+5], a6 = b_dec[d0+6], a7 = b_dec[d0+7];
        for (int j = 0; j < kk; j++) {
            int ci = s_fIdx[j];
            float v = s_fVal[j];
            uint4 pw = *(const uint4*)(&g_WnT16[(size_t)ci * D + d0]);
            __half2 h0 = *(__half2*)&pw.x, h1 = *(__half2*)&pw.y;
            __half2 h2 = *(__half2*)&pw.z, h3 = *(__half2*)&pw.w;
            float2 f0 = __half22float2(h0), f1 = __half22float2(h1);
            float2 f2 = __half22float2(h2), f3 = __half22float2(h3);
            a0 += v * f0.x; a1 += v * f0.y; a2 += v * f1.x; a3 += v * f1.y;
            a4 += v * f2.x; a5 += v * f2.y; a6 += v * f3.x; a7 += v * f3.y;
        }
        float4 o0 = make_float4(a0, a1, a2, a3);
        float4 o1 = make_float4(a4, a5, a6, a7);
        *(float4*)(out + (size_t)row * D + d0) = o0;
        *(float4*)(out + (size_t)row * D + d0 + 4) = o1;
    }
}

// ---------------------------------------------------------------------------
// Launch — hgemm at profiled slot #4
// ---------------------------------------------------------------------------
extern "C" void kernel_launch(void* const* d_in, const int* in_sizes, int n_in,
                              void* d_out, int out_size) {
    const float* x = (const float*)d_in[0];
    const float* W_enc = (const float*)d_in[1];
    const float* gamma = (const float*)d_in[3];
    const float* beta = (const float*)d_in[4];
    const float* W_dec = (const float*)d_in[5];
    const float* b_dec = (const float*)d_in[6];
    const int* topk = (const int*)d_in[7];

    int D = in_sizes[6];
    int C = in_sizes[2];
    int B = in_sizes[0] / D;
    float* out = (float*)d_out;

    int nx = B * D, nw = C * D;
    split_all_kernel<<<(nx + nw + 255) / 256, 256>>>(x, W_enc, nx, nw);  // #1

    colnorm_kernel<<<(C + 255) / 256, 256>>>(W_dec, D, C);               // #2

    dim3 tg((C + 31) / 32, (D + 31) / 32);
    transpose_kernel<<<tg, dim3(32, 8)>>>(W_dec, D, C);                  // #3

    cudaFuncSetAttribute(hgemm_kernel,
                         cudaFuncAttributeMaxDynamicSharedMemorySize, GEMM_SMEM);
    dim3 gg(B / 128, C / 128);
    hgemm_kernel<<<gg, 256, GEMM_SMEM>>>(B, C, D);                       // #4 (profiled)

    stats_final_kernel<<<(C + 255) / 256, 256>>>(gamma, beta, B, C, B / 128);  // #5

    size_t dynSel = (size_t)C * sizeof(float) + 2048 * sizeof(unsigned) + 256 * sizeof(unsigned);
    cudaFuncSetAttribute(topk_select_kernel,
                         cudaFuncAttributeMaxDynamicSharedMemorySize, (int)dynSel);
    topk_select_kernel<<<B, 256, dynSel>>>(topk, C);                     // #6

    scan_kernel<<<1, 256>>>(C);                                          // #7
    scatter_kernel<<<B, 256>>>();                                        // #8

    int maxPairs = B * NCAND;
    refine2_kernel<<<(maxPairs + 255) / 256, 256>>>(x, W_enc, D);        // #9
    decode_kernel<<<B, 256>>>(b_dec, topk, out, C, D);                   // #10
}

// round 17
// speedup vs baseline: 1.1104x; 1.1104x over previous
#include <cuda_runtime.h>
#include <cuda_fp16.h>
#include <cstdint>

// B=4096, D(K)=2048, C=16384, topk=64
// recon = TopK(BN(x @ W_enc^T)) @ normalize_cols(W_dec)^T + b_dec
// b_enc cancels inside batch-norm -> skipped everywhere (consistent).
//
// Numerics ledger (R4..R16):
//  - BN stats: fp64 reduction of split-fp16 fp32 GEMM accumulators (3-product
//    split is load-bearing for stats: R5 failed with 1-product-accuracy h).
//  - Candidates tolerate ~3e-4 noise -> h stored fp16; margin 8 = 140 sigma.
//  - Refinement: serial ascending-k fp32 FMA chain, block-per-row with smem
//    xrow (R16 falsified the column-sorted layout).
//  - GEMM: R11 inner order optimal (R12/R14 falsified reorders).
//  - WnT fp16: +2e-4 rel_err (R15, accepted).
// R17: R15 baseline + margin 16->8 + 512-thread select.

#define MAX_B 4096
#define MAX_C 16384
#define MAX_D 2048
#define MAX_MT 32
#define NCAND 160
#define SELT 512

__device__ __half g_h16[(size_t)MAX_B * MAX_C];
__device__ __half g_WnT16[(size_t)MAX_C * MAX_D];
__device__ float g_inv_norm[MAX_C];
__device__ float g_scale[MAX_C];
__device__ float g_bias[MAX_C];
__device__ double g_psum[MAX_MT * MAX_C];
__device__ double g_psumsq[MAX_MT * MAX_C];
__device__ __half g_xh[(size_t)MAX_B * MAX_D];
__device__ __half g_xl[(size_t)MAX_B * MAX_D];
__device__ __half g_wh[(size_t)MAX_C * MAX_D];
__device__ __half g_wl[(size_t)MAX_C * MAX_D];
__device__ int g_candIdx[(size_t)MAX_B * NCAND];
__device__ int g_candCnt[MAX_B];

// ---------------------------------------------------------------------------
__global__ void split_all_kernel(const float* __restrict__ x,
                                 const float* __restrict__ W, int nx, int nw) {
    int i = blockIdx.x * blockDim.x + threadIdx.x;
    if (i < nx) {
        float s = x[i] * 4096.0f;                // 2^12, exact
        __half h = __float2half_rn(s);
        g_xh[i] = h;
        g_xl[i] = __float2half_rn(s - __half2float(h));
    } else if (i < nx + nw) {
        int j = i - nx;
        float s = W[j] * 262144.0f;              // 2^18, exact
        __half h = __float2half_rn(s);
        g_wh[j] = h;
        g_wl[j] = __float2half_rn(s - __half2float(h));
    }
}

// ---------------------------------------------------------------------------
__global__ void colnorm_kernel(const float* __restrict__ Wdec, int D, int C) {
    int c = blockIdx.x * blockDim.x + threadIdx.x;
    if (c >= C) return;
    double s0 = 0, s1 = 0, s2 = 0, s3 = 0;
    int d = 0;
    for (; d + 3 < D; d += 4) {
        float w0 = Wdec[(size_t)(d + 0) * C + c];
        float w1 = Wdec[(size_t)(d + 1) * C + c];
        float w2 = Wdec[(size_t)(d + 2) * C + c];
        float w3 = Wdec[(size_t)(d + 3) * C + c];
        s0 += (double)w0 * w0; s1 += (double)w1 * w1;
        s2 += (double)w2 * w2; s3 += (double)w3 * w3;
    }
    for (; d < D; d++) { float w = Wdec[(size_t)d * C + c]; s0 += (double)w * w; }
    double n = sqrt(s0 + s1 + s2 + s3);
    if (n < 1e-12) n = 1e-12;
    g_inv_norm[c] = (float)(1.0 / n);
}

// ---------------------------------------------------------------------------
__global__ void transpose_kernel(const float* __restrict__ Wdec, int D, int C) {
    __shared__ float tile[32][33];
    int c0 = blockIdx.x * 32, d0 = blockIdx.y * 32;
    for (int i = threadIdx.y; i < 32; i += 8) {
        int d = d0 + i, c = c0 + threadIdx.x;
        tile[i][threadIdx.x] = (d < D && c < C) ? Wdec[(size_t)d * C + c] : 0.f;
    }
    __syncthreads();
    for (int i = threadIdx.y; i < 32; i += 8) {
        int c = c0 + i, d = d0 + threadIdx.x;
        if (c < C && d < D)
            g_WnT16[(size_t)c * D + d] =
                __float2half_rn(tile[threadIdx.x][i] * g_inv_norm[c]);
    }
}

// ---------------------------------------------------------------------------
// mma.sync split-fp16 GEMM (R11 inner order — best measured: 2156us)
// ---------------------------------------------------------------------------
#define BKH 32
#define MAT_BYTES 8192
#define STAGE_BYTES 32768
#define STAGES 3
#define GEMM_SMEM (STAGES * STAGE_BYTES)

#define LDSM4(R0, R1, R2, R3, ADDR) \
    asm volatile("ldmatrix.sync.aligned.m8n8.x4.shared.b16 {%0,%1,%2,%3}, [%4];" \
                 : "=r"(R0), "=r"(R1), "=r"(R2), "=r"(R3) : "r"(ADDR))

#define MMA16816(CC, A0, A1, A2, A3, B0, B1) \
    asm volatile("mma.sync.aligned.m16n8k16.row.col.f32.f16.f16.f32 " \
                 "{%0,%1,%2,%3}, {%4,%5,%6,%7}, {%8,%9}, {%0,%1,%2,%3};" \
                 : "+f"((CC)[0]), "+f"((CC)[1]), "+f"((CC)[2]), "+f"((CC)[3]) \
                 : "r"(A0), "r"(A1), "r"(A2), "r"(A3), "r"(B0), "r"(B1))

__device__ __forceinline__ uint32_t smem_u32(const void* p) {
    uint32_t a;
    asm("{ .reg .u64 t; cvta.to.shared.u64 t, %1; cvt.u32.u64 %0, t; }" : "=r"(a) : "l"(p));
    return a;
}
__device__ __forceinline__ uint32_t swz64(uint32_t base, int row, int kbyte) {
    uint32_t off = row * 64 + kbyte;
    return base + (off ^ ((off >> 3) & 0x30));
}
__device__ __forceinline__ void cpasync16(uint32_t sa, const void* g) {
    asm volatile("cp.async.cg.shared.global [%0], [%1], 16;" :: "r"(sa), "l"(g));
}

__device__ __forceinline__ void load_stage(uint32_t sbase, int m0, int n0,
                                           int k0, int K, int tid) {
    const __half* srcs[4] = {g_xh, g_xl, g_wh, g_wl};
    int r0s[4] = {m0, m0, n0, n0};
#pragma unroll
    for (int mat = 0; mat < 4; mat++) {
        const __half* src = srcs[mat];
        int r0 = r0s[mat];
#pragma unroll
        for (int s = 0; s < 2; s++) {
            int idx = tid * 2 + s;
            int row = idx >> 2, seg = idx & 3;
            const __half* g = src + (size_t)(r0 + row) * K + k0 + seg * 8;
            cpasync16(swz64(sbase + mat * MAT_BYTES, row, seg * 16), g);
        }
    }
}

__global__ __launch_bounds__(256, 2)
void hgemm_kernel(int M, int N, int K) {
    extern __shared__ __align__(1024) char smem[];
    const uint32_t sb = smem_u32(smem);
    const int tid = threadIdx.x;
    const int wid = tid >> 5, lane = tid & 31;
    const int wm = (wid & 1) * 64;
    const int wn = (wid >> 1) * 32;
    const int m0 = blockIdx.x * 128;
    const int n0 = blockIdx.y * 128;
    const int grp = lane >> 3, lr = lane & 7;
    const int NK = K / BKH;

    float acc[4][4][4];
#pragma unroll
    for (int i = 0; i < 4; i++)
#pragma unroll
        for (int j = 0; j < 4; j++)
#pragma unroll
            for (int q = 0; q < 4; q++) acc[i][j][q] = 0.f;

#pragma unroll
    for (int s = 0; s < STAGES - 1; s++) {
        load_stage(sb + s * STAGE_BYTES, m0, n0, s * BKH, K, tid);
        asm volatile("cp.async.commit_group;");
    }

    for (int ch = 0; ch < NK; ch++) {
        asm volatile("cp.async.wait_group %0;" :: "n"(STAGES - 2));
        __syncthreads();

        int pf = ch + STAGES - 1;
        if (pf < NK)
            load_stage(sb + (pf % STAGES) * STAGE_BYTES, m0, n0, pf * BKH, K, tid);
        asm volatile("cp.async.commit_group;");

        uint32_t sa = sb + (ch % STAGES) * STAGE_BYTES;
        uint32_t aH = sa, aL = sa + MAT_BYTES;
        uint32_t bH = sa + 2 * MAT_BYTES, bL = sa + 3 * MAT_BYTES;

#pragma unroll
        for (int ks = 0; ks < 2; ks++) {
            int kb = ks * 32;
            uint32_t Bh[4][2], Bl[4][2];
#pragma unroll
            for (int np = 0; np < 2; np++) {
                int nrow = wn + np * 16 + (grp >> 1) * 8 + lr;
                int kbyte = kb + (grp & 1) * 16;
                uint32_t r0, r1, r2, r3;
                LDSM4(r0, r1, r2, r3, swz64(bH, nrow, kbyte));
                Bh[np * 2][0] = r0; Bh[np * 2][1] = r1;
                Bh[np * 2 + 1][0] = r2; Bh[np * 2 + 1][1] = r3;
                LDSM4(r0, r1, r2, r3, swz64(bL, nrow, kbyte));
                Bl[np * 2][0] = r0; Bl[np * 2][1] = r1;
                Bl[np * 2 + 1][0] = r2; Bl[np * 2 + 1][1] = r3;
            }
#pragma unroll
            for (int mi = 0; mi < 4; mi++) {
                int arow = wm + mi * 16 + (grp & 1) * 8 + lr;
                int kbyte = kb + (grp >> 1) * 16;
                uint32_t a0, a1, a2, a3, l0, l1, l2, l3;
                LDSM4(a0, a1, a2, a3, swz64(aH, arow, kbyte));
                LDSM4(l0, l1, l2, l3, swz64(aL, arow, kbyte));
#pragma unroll
                for (int ni = 0; ni < 4; ni++)
                    MMA16816(acc[mi][ni], a0, a1, a2, a3, Bh[ni][0], Bh[ni][1]);
#pragma unroll
                for (int ni = 0; ni < 4; ni++)
                    MMA16816(acc[mi][ni], a0, a1, a2, a3, Bl[ni][0], Bl[ni][1]);
#pragma unroll
                for (int ni = 0; ni < 4; ni++)
                    MMA16816(acc[mi][ni], l0, l1, l2, l3, Bh[ni][0], Bh[ni][1]);
            }
        }
        __syncthreads();
    }

    const float sc = 9.313225746154785e-10f;  // 2^-30
    int gid = lane >> 2, tig = lane & 3;
#pragma unroll
    for (int mi = 0; mi < 4; mi++) {
#pragma unroll
        for (int ni = 0; ni < 4; ni++) {
            int r = m0 + wm + mi * 16 + gid;
            int c = n0 + wn + ni * 8 + tig * 2;
            *(__half2*)&g_h16[(size_t)r * N + c] =
                __floats2half2_rn(acc[mi][ni][0] * sc, acc[mi][ni][1] * sc);
            *(__half2*)&g_h16[(size_t)(r + 8) * N + c] =
                __floats2half2_rn(acc[mi][ni][2] * sc, acc[mi][ni][3] * sc);
        }
    }

    double csum[4][2], csq[4][2];
#pragma unroll
    for (int ni = 0; ni < 4; ni++)
#pragma unroll
        for (int qc = 0; qc < 2; qc++) {
            double s = 0.0, q = 0.0;
#pragma unroll
            for (int mi = 0; mi < 4; mi++) {
                double v1 = (double)(acc[mi][ni][qc]) * (double)sc;
                double v2 = (double)(acc[mi][ni][qc + 2]) * (double)sc;
                s += v1 + v2;
                q += v1 * v1 + v2 * v2;
            }
            csum[ni][qc] = s; csq[ni][qc] = q;
        }
#pragma unroll
    for (int off = 4; off <= 16; off <<= 1) {
#pragma unroll
        for (int ni = 0; ni < 4; ni++)
#pragma unroll
            for (int qc = 0; qc < 2; qc++) {
                csum[ni][qc] += __shfl_xor_sync(0xffffffffu, csum[ni][qc], off);
                csq[ni][qc]  += __shfl_xor_sync(0xffffffffu, csq[ni][qc], off);
            }
    }
    __syncthreads();
    double* scs = (double*)smem;
    double* scq = scs + 256;
    if (gid == 0) {
#pragma unroll
        for (int ni = 0; ni < 4; ni++)
#pragma unroll
            for (int qc = 0; qc < 2; qc++) {
                int cl = wn + ni * 8 + tig * 2 + qc;
                scs[(wid & 1) * 128 + cl] = csum[ni][qc];
                scq[(wid & 1) * 128 + cl] = csq[ni][qc];
            }
    }
    __syncthreads();
    if (tid < 128) {
        int mt = blockIdx.x;
        g_psum[(size_t)mt * N + n0 + tid]   = scs[tid] + scs[128 + tid];
        g_psumsq[(size_t)mt * N + n0 + tid] = scq[tid] + scq[128 + tid];
    }
}

// ---------------------------------------------------------------------------
__global__ void stats_final_kernel(const float* __restrict__ gamma,
                                   const float* __restrict__ beta,
                                   int Bsz, int C, int nslot) {
    int c = blockIdx.x * blockDim.x + threadIdx.x;
    if (c >= C) return;
    double s = 0, q = 0;
    for (int i = 0; i < nslot; i++) {
        s += g_psum[(size_t)i * C + c];
        q += g_psumsq[(size_t)i * C + c];
    }
    double mean = s / (double)Bsz;
    double var = q / (double)Bsz - mean * mean;
    double inv = 1.0 / sqrt(var + 1e-5);
    float sc = (float)((double)gamma[c] * inv);
    g_scale[c] = sc;
    g_bias[c] = beta[c] - (float)mean * sc;
}

// ---------------------------------------------------------------------------
// topk_select: 512 threads, margin 8
// ---------------------------------------------------------------------------
__global__ __launch_bounds__(SELT) void topk_select_kernel(
    const int* __restrict__ topk_p, int C) {
    extern __shared__ float sm[];
    float* vals = sm;
    unsigned* hist = (unsigned*)(vals + C);
    unsigned* chunks = hist + 2048;

    __shared__ int s_selIdx[NCAND];
    __shared__ int s_eqIdx[256];
    __shared__ int s_nsel, s_neq, s_need, s_chunk, s_flagzero;
    __shared__ unsigned s_prefix;

    int row = blockIdx.x;
    int tid = threadIdx.x;
    int k = *topk_p;
    if (k > C) k = C;
    if (k > 128) k = 128;
    int kc = k + 8;
    if (kc > C) kc = C;
    if (kc > NCAND) kc = NCAND;

    for (int c = tid; c < C; c += SELT) {
        float v = __half2float(g_h16[(size_t)row * C + c]);
        v = v * g_scale[c] + g_bias[c];
        vals[c] = (v > 0.f) ? v : 0.f;
    }
    if (tid == 0) { s_nsel = 0; s_neq = 0; s_need = kc; s_prefix = 0u; s_flagzero = 0; }
    __syncthreads();

    {
        const int shifts[3] = {21, 10, 0};
        const int nbitsA[3] = {11, 11, 10};
        const unsigned maskHi[3] = {0u, 0xFFE00000u, 0xFFFFFC00u};

        for (int r = 0; r < 3; r++) {
            int nb = 1 << nbitsA[r];
            for (int i = tid; i < nb; i += SELT) hist[i] = 0u;
            __syncthreads();

            unsigned pre = s_prefix, mh = maskHi[r], msk = (unsigned)(nb - 1);
            int sh = shifts[r];
            for (int c = tid; c < C; c += SELT) {
                unsigned key = __float_as_uint(vals[c]);
                if (key != 0u && (key & mh) == pre)
                    atomicAdd(&hist[(key >> sh) & msk], 1u);
            }
            __syncthreads();

            int NCH = nb >> 3;   // <= 256
            unsigned csum = 0u;
            if (tid < NCH) {
#pragma unroll
                for (int j = 0; j < 8; j++) csum += hist[tid * 8 + j];
                chunks[tid] = csum;
            }
            __syncthreads();
            for (int off = 1; off < NCH; off <<= 1) {
                unsigned add = 0u;
                if (tid < NCH && tid + off < NCH) add = chunks[tid + off];
                __syncthreads();
                if (tid < NCH) chunks[tid] += add;
                __syncthreads();
            }

            int need = s_need;
            if (tid < NCH) {
                int incl = (int)chunks[tid];
                int excl = incl - (int)csum;
                if (excl < need && incl >= need) s_chunk = tid;
                if (tid == 0 && incl < need) s_flagzero = 1;
            }
            __syncthreads();
            if (s_flagzero) break;

            if (tid == 0) {
                int t = s_chunk;
                unsigned cs = 0u;
#pragma unroll
                for (int j = 0; j < 8; j++) cs += hist[t * 8 + j];
                int cum = (int)chunks[t] - (int)cs;
                for (int j = 7; j >= 0; j--) {
                    int hc = (int)hist[t * 8 + j];
                    cum += hc;
                    if (cum >= need) {
                        s_prefix |= ((unsigned)(t * 8 + j)) << sh;
                        s_need = need - (cum - hc);
                        break;
                    }
                }
            }
            __syncthreads();
        }
        __syncthreads();

        unsigned T = s_prefix;
        int need_eq = s_need;
        bool zeroThresh = (s_flagzero != 0);

        for (int c = tid; c < C; c += SELT) {
            unsigned key = __float_as_uint(vals[c]);
            if (key == 0u) continue;
            if (zeroThresh || key > T) {
                int p = atomicAdd(&s_nsel, 1);
                if (p < NCAND) s_selIdx[p] = c;
            } else if (key == T) {
                int p = atomicAdd(&s_neq, 1);
                if (p < 256) s_eqIdx[p] = c;
            }
        }
        __syncthreads();

        if (!zeroThresh && tid == 0) {
            int ne = s_neq; if (ne > 256) ne = 256;
            for (int i = 1; i < ne; i++) {
                int v = s_eqIdx[i]; int j = i - 1;
                while (j >= 0 && s_eqIdx[j] > v) { s_eqIdx[j + 1] = s_eqIdx[j]; j--; }
                s_eqIdx[j + 1] = v;
            }
            int take = need_eq; if (take > ne) take = ne;
            int base = s_nsel;
            for (int i = 0; i < take; i++) {
                int p = base + i;
                if (p < NCAND) s_selIdx[p] = s_eqIdx[i];
            }
            s_nsel = base + take;
        }
        __syncthreads();
    }

    int ncand = s_nsel; if (ncand > NCAND) ncand = NCAND;
    if (tid < ncand) g_candIdx[(size_t)row * NCAND + tid] = s_selIdx[tid];
    if (tid == 0) g_candCnt[row] = ncand;
}

// ---------------------------------------------------------------------------
// refine_decode: exact serial fp32 chain refinement, exact rank, fp16 WnT decode.
// ---------------------------------------------------------------------------
__global__ __launch_bounds__(256) void refine_decode_kernel(
    const float* __restrict__ x, const float* __restrict__ W_enc,
    const float* __restrict__ b_dec, const int* __restrict__ topk_p,
    float* __restrict__ out, int C, int D) {
    __shared__ float xrow[MAX_D];
    __shared__ int s_idx[NCAND];
    __shared__ float s_val[NCAND];
    __shared__ int s_fIdx[128];
    __shared__ float s_fVal[128];

    int row = blockIdx.x;
    int tid = threadIdx.x;
    int k = *topk_p;
    if (k > C) k = C;
    if (k > 128) k = 128;

    int ncand = g_candCnt[row];
    if (ncand > NCAND) ncand = NCAND;
    if (tid < ncand) s_idx[tid] = g_candIdx[(size_t)row * NCAND + tid];
    for (int d = tid; d < D; d += 256) xrow[d] = x[(size_t)row * D + d];
    __syncthreads();

    int myc = (tid < ncand) ? s_idx[tid] : -1;

    if (myc >= 0) {
        const float4* wr = (const float4*)(W_enc + (size_t)myc * D);
        const int NIT = D >> 2;
        float facc = 0.f;
#pragma unroll 4
        for (int i = 0; i < NIT; i++) {
            float4 w = wr[i];
            const float* xq = &xrow[i << 2];
            facc = __fmaf_rn(xq[0], w.x, facc);
            facc = __fmaf_rn(xq[1], w.y, facc);
            facc = __fmaf_rn(xq[2], w.z, facc);
            facc = __fmaf_rn(xq[3], w.w, facc);
        }
        float bn = __fmaf_rn(facc, g_scale[myc], g_bias[myc]);
        s_val[tid] = (bn > 0.f) ? bn : 0.f;
    }
    __syncthreads();

    int kk = (k < ncand) ? k : ncand;
    if (tid < ncand) {
        float vj = s_val[tid]; int cj = myc;
        int rank = 0;
        for (int i = 0; i < ncand; i++) {
            float vi = s_val[i]; int ci = s_idx[i];
            if (vi > vj || (vi == vj && ci < cj)) rank++;
        }
        if (rank < kk) { s_fVal[rank] = vj; s_fIdx[rank] = cj; }
    }
    __syncthreads();

    int d0 = tid * 8;   // D=2048 covered by 256 threads x 8
    if (d0 + 7 < D) {
        float a0 = b_dec[d0], a1 = b_dec[d0+1], a2 = b_dec[d0+2], a3 = b_dec[d0+3];
        float a4 = b_dec[d0+4], a5 = b_dec[d0+5], a6 = b_dec[d0+6], a7 = b_dec[d0+7];
        for (int j = 0; j < kk; j++) {
            int ci = s_fIdx[j];
            float v = s_fVal[j];
            uint4 pw = *(const uint4*)(&g_WnT16[(size_t)ci * D + d0]);
            __half2 h0 = *(__half2*)&pw.x, h1 = *(__half2*)&pw.y;
            __half2 h2 = *(__half2*)&pw.z, h3 = *(__half2*)&pw.w;
            float2 f0 = __half22float2(h0), f1 = __half22float2(h1);
            float2 f2 = __half22float2(h2), f3 = __half22float2(h3);
            a0 += v * f0.x; a1 += v * f0.y; a2 += v * f1.x; a3 += v * f1.y;
            a4 += v * f2.x; a5 += v * f2.y; a6 += v * f3.x; a7 += v * f3.y;
        }
        float4 o0 = make_float4(a0, a1, a2, a3);
        float4 o1 = make_float4(a4, a5, a6, a7);
        *(float4*)(out + (size_t)row * D + d0) = o0;
        *(float4*)(out + (size_t)row * D + d0 + 4) = o1;
    }
}

// ---------------------------------------------------------------------------
// Launch — hgemm at profiled slot #4
// ---------------------------------------------------------------------------
extern "C" void kernel_launch(void* const* d_in, const int* in_sizes, int n_in,
                              void* d_out, int out_size) {
    const float* x = (const float*)d_in[0];
    const float* W_enc = (const float*)d_in[1];
    const float* gamma = (const float*)d_in[3];
    const float* beta = (const float*)d_in[4];
    const float* W_dec = (const float*)d_in[5];
    const float* b_dec = (const float*)d_in[6];
    const int* topk = (const int*)d_in[7];

    int D = in_sizes[6];
    int C = in_sizes[2];
    int B = in_sizes[0] / D;
    float* out = (float*)d_out;

    int nx = B * D, nw = C * D;
    split_all_kernel<<<(nx + nw + 255) / 256, 256>>>(x, W_enc, nx, nw);  // #1

    colnorm_kernel<<<(C + 255) / 256, 256>>>(W_dec, D, C);               // #2

    dim3 tg((C + 31) / 32, (D + 31) / 32);
    transpose_kernel<<<tg, dim3(32, 8)>>>(W_dec, D, C);                  // #3

    cudaFuncSetAttribute(hgemm_kernel,
                         cudaFuncAttributeMaxDynamicSharedMemorySize, GEMM_SMEM);
    dim3 gg(B / 128, C / 128);
    hgemm_kernel<<<gg, 256, GEMM_SMEM>>>(B, C, D);                       // #4 (profiled)

    stats_final_kernel<<<(C + 255) / 256, 256>>>(gamma, beta, B, C, B / 128);  // #5

    size_t dynSel = (size_t)C * sizeof(float) + 2048 * sizeof(unsigned) + 256 * sizeof(unsigned);
    cudaFuncSetAttribute(topk_select_kernel,
                         cudaFuncAttributeMaxDynamicSharedMemorySize, (int)dynSel);
    topk_select_kernel<<<B, SELT, dynSel>>>(topk, C);                    // #6

    refine_decode_kernel<<<B, 256>>>(x, W_enc, b_dec, topk, out, C, D);  // #7
}